// round 10
// baseline (speedup 1.0000x reference)
#include <cuda_runtime.h>
#include <cstdint>

// ----------------------------------------------------------------------------
// HashingDiscretizer — R10.
// Verified env: keys int32, output f32 concat [out_keys | out_vals] (2*nnz),
// feature_ids == arange(F) (runtime-verified; fallbacks kept).
// R10: level-1 splitters live in SHARED MEMORY as bf16 (round-down) -> the
// global gather is ONE 32B leaf sector per calibrated element. Leaves carry
// an exact f32 guard; rare bf16 over-count fixed by a pair-uniform retry.
// Persistent grid: 1 CTA/SM, 1024 threads, 128KB dynamic smem.
// ----------------------------------------------------------------------------

static constexpr int  LUT_SIZE = 65536;
static constexpr int  NBIN     = 63;
static constexpr int  ROW      = 72;        // legacy btree (fallback paths)
static constexpr int  MAX_F    = 8192;
static constexpr unsigned GOLDEN = 0x9E3779B9u;
static constexpr unsigned OUT_MASK_U = 0x3FFFFFu;        // (1<<22)-1

__device__ int g_is64 = 0;
__device__ int g_not_arange = 0;  // monotone 0->1 via atomicOr (deterministic)
__device__ unsigned short g_lut[LUT_SIZE];               // fallback LUT
__device__ __align__(32) float g_btree[MAX_F * ROW];     // fallback btree
__device__ __align__(16) unsigned short g_spl16[MAX_F * 8]; // bf16 splitters
__device__ __align__(32) float g_leafg[MAX_F * 64];      // guarded leaves

// bf16 round toward -inf (so stored splitter <= true splitter)
__device__ __forceinline__ unsigned short bf16_rd(float x) {
    unsigned b = __float_as_uint(x);
    unsigned hi = b >> 16;
    if ((b & 0x80000000u) && (b & 0xFFFFu)) hi++;   // negative: round away
    return (unsigned short)hi;
}

// ---- K1: fused probe + arange-check + LUT + legacy btree + spl16 + leaves --
__global__ void build_tables(const void* __restrict__ fids,
                             const float* __restrict__ bins,
                             int F, int total_max, int force64) {
    int t = blockIdx.x * blockDim.x + threadIdx.x;

    const int* fw = (const int*)fids;
    const bool is64 = force64 || (fw[1] == 0 && fw[3] == 0);
    if (t == 0) g_is64 = is64 ? 1 : 0;

    const long long* f64p = (const long long*)fids;
    const int*       f32p = (const int*)fids;

    if (t < LUT_SIZE) {
        if (t < F) {
            long long fv = is64 ? f64p[t] : (long long)f32p[t];
            if (fv != (long long)t) atomicOr(&g_not_arange, 1);
        }
        long long key = (long long)t;
        int lo = 0, hi = F;
        while (lo < hi) {
            int mid = (lo + hi) >> 1;
            long long fv = is64 ? f64p[mid] : (long long)f32p[mid];
            if (fv < key) lo = mid + 1; else hi = mid;
        }
        int idx = lo < (F - 1) ? lo : (F - 1);
        long long fv = is64 ? f64p[idx] : (long long)f32p[idx];
        unsigned short v = (unsigned short)(idx & 0x7FFF);
        if (fv == key) v |= 0x8000u;
        g_lut[t] = v;
    }
    // legacy btree (fallback paths): [0..7] splitters+INF, [8+8c+p] leaves+INF
    if (t < F * ROW) {
        int f = t / ROW;
        int j = t - f * ROW;
        const float INF = __int_as_float(0x7f800000);
        float v;
        if (j < 8) {
            v = (j < 7) ? __ldg(&bins[f * NBIN + 8 * j + 7]) : INF;
        } else {
            int q = j - 8, l = q >> 3, p = q & 7;
            v = (p < 7) ? __ldg(&bins[f * NBIN + 8 * l + p]) : INF;
        }
        g_btree[t] = v;
    }
    // bf16 splitters: row r = 8 ushorts [s'_0..s'_6, +INF]
    if (t < F * 8) {
        int r = t >> 3, j = t & 7;
        unsigned short h = (j < 7) ? bf16_rd(__ldg(&bins[r * NBIN + 8 * j + 7]))
                                   : (unsigned short)0x7F80;   // +inf bf16
        g_spl16[t] = h;
    }
    // guarded leaves: row r = 8 leaves x 8 floats [guard, b0..b6]
    if (t < F * 64) {
        int r = t >> 6, q = t & 63, m = q >> 3, p = q & 7;
        float v;
        if (p == 0) v = (m == 0) ? __int_as_float(0xFF800000)   // -inf
                                 : __ldg(&bins[r * NBIN + 8 * m - 1]);
        else        v = __ldg(&bins[r * NBIN + 8 * m + p - 1]);
        g_leafg[t] = v;
    }
    (void)total_max;
}

// ---- generic per-element path (fallback configs + tails) -------------------
template <bool AR>
__device__ __forceinline__ void process_one(long long k, float v, int F,
                                            unsigned& okey, float& oval) {
    unsigned long long u = (unsigned long long)k;
    bool cal; int idx;
    if (AR) { cal = u < (unsigned long long)F; idx = (int)u; }
    else {
        if (u < (unsigned long long)LUT_SIZE) {
            unsigned short e = g_lut[u];
            cal = (e & 0x8000u) != 0; idx = (int)(e & 0x7FFFu);
        } else { cal = false; idx = 0; }
    }
    if (cal) {
        const float* nb = g_btree + idx * ROW;
        float4 s0 = *(const float4*)(nb);
        float4 s1 = *(const float4*)(nb + 4);
        int c = (s0.x < v) + (s0.y < v) + (s0.z < v) + (s0.w < v)
              + (s1.x < v) + (s1.y < v) + (s1.z < v) + (s1.w < v);
        const float* lf = nb + 8 + c * 8;
        float4 l0 = *(const float4*)(lf);
        float4 l1 = *(const float4*)(lf + 4);
        int bin = c * 8
              + (l0.x < v) + (l0.y < v) + (l0.z < v) + (l0.w < v)
              + (l1.x < v) + (l1.y < v) + (l1.z < v) + (l1.w < v);
        unsigned h = ((unsigned)u * GOLDEN + (unsigned)bin) * GOLDEN;
        okey = h & OUT_MASK_U; oval = 1.0f;
    } else {
        okey = (unsigned)(u & (unsigned long long)OUT_MASK_U);
        oval = v;
    }
}

// ---- main kernel: persistent, smem level-1, 1-sector guarded leaf ----------
__global__ void __launch_bounds__(1024, 1)
hashing_smem_kernel(const void* __restrict__ keysv,
                    const float* __restrict__ valsv,
                    int nnz, void* __restrict__ outv, int F) {
    extern __shared__ uint2 s_spl[];   // F rows x 16B (as 2x uint2 per row)
    const bool hot = (g_is64 == 0) && (g_not_arange == 0);
    int tid = threadIdx.x;

    if (hot) {
        // fill smem splitter table (coalesced, L2-hot)
        const uint2* src = (const uint2*)g_spl16;
        for (int i = tid; i < F * 2; i += blockDim.x) s_spl[i] = src[i];
        __syncthreads();

        const int*   keys = (const int*)keysv;
        const float* vals = valsv;
        float*       out  = (float*)outv;

        int lane = tid & 31, half = lane & 1, pair = lane >> 1;
        unsigned pmask = 0x3u << (2 * pair);
        int wid = tid >> 5;
        int nwarps = gridDim.x * (blockDim.x >> 5);
        int gwarp  = blockIdx.x * (blockDim.x >> 5) + wid;
        int ntiles = nnz >> 6;                    // full 64-elem tiles

        for (int tile = gwarp; tile < ntiles; tile += nwarps) {
            int base = tile * 64 + pair * 4;
            int4   kk = __ldcs((const int4*)(keys + base));
            float4 vv = __ldcs((const float4*)(vals + base));
            int   k[4] = {kk.x, kk.y, kk.z, kk.w};
            float v[4] = {vv.x, vv.y, vv.z, vv.w};

            // ---- level 1: smem bf16 splitters, counts packed 8b x 4 ----
            unsigned packed = 0;
            #pragma unroll
            for (int j = 0; j < 4; j++) {
                unsigned u = (unsigned)k[j];
                bool cal = u < (unsigned)F;           // pair-uniform
                int row = cal ? (int)u : 0;
                uint2 w = s_spl[row * 2 + half];
                float vj = v[j];
                float a0 = __uint_as_float(w.x << 16);
                float a1 = __uint_as_float(w.x & 0xFFFF0000u);
                float a2 = __uint_as_float(w.y << 16);
                float a3 = __uint_as_float(w.y & 0xFFFF0000u);
                int cnt = (a0 < vj) + (a1 < vj) + (a2 < vj) + (a3 < vj);
                cnt = cal ? cnt : 0;
                packed |= (unsigned)cnt << (8 * j);
            }
            unsigned csum = packed + __shfl_xor_sync(pmask, packed, 1);

            // ---- level 2: one 32B guarded leaf per element ----
            float ok[4], ov[4];
            #pragma unroll
            for (int j = 0; j < 4; j++) {
                unsigned u = (unsigned)k[j];
                float vj = v[j];
                if (u < (unsigned)F) {                // pair-uniform branch
                    int c = (int)((csum >> (8 * j)) & 0xFFu);  // in [0,7]
                    const float4* lp = (const float4*)(g_leafg + (int)u * 64);
                    int bin;
                    for (;;) {
                        float4 l = lp[c * 2 + half];
                        // half0: l = [guard,b0,b1,b2]; half1: l = [b3,b4,b5,b6]
                        int cnt2  = (l.y < vj) + (l.z < vj) + (l.w < vj);
                        int first = (l.x < vj) ? 1 : 0;
                        unsigned m = half
                            ? (unsigned)(cnt2 + first)
                            : ((unsigned)cnt2 |
                               (((first == 0) && (c > 0)) ? 64u : 0u));
                        unsigned s2 = m + __shfl_xor_sync(pmask, m, 1);
                        if (s2 & 64u) { c--; continue; }   // rare bf16 fixup
                        bin = c * 8 + (int)(s2 & 63u);
                        break;
                    }
                    unsigned h = (u * GOLDEN + (unsigned)bin) * GOLDEN;
                    ok[j] = (float)(h & OUT_MASK_U);
                    ov[j] = 1.0f;
                } else {
                    ok[j] = (float)(u & OUT_MASK_U);
                    ov[j] = vj;
                }
            }
            if (half == 0)
                __stcs((float4*)(out + base),
                       make_float4(ok[0], ok[1], ok[2], ok[3]));
            else
                __stcs((float4*)(out + nnz + base),
                       make_float4(ov[0], ov[1], ov[2], ov[3]));
        }
        // ragged tail (none for nnz % 64 == 0)
        int tailStart = ntiles << 6;
        if (gwarp == 0) {
            for (int i = tailStart + lane; i < nnz; i += 32) {
                unsigned okk; float ovv;
                process_one<true>((long long)keys[i], vals[i], F, okk, ovv);
                out[i] = (float)okk;
                out[nnz + i] = ovv;
            }
        }
    } else {
        // fallback configs: grid-stride scalar over elements
        const bool is64 = (g_is64 != 0);
        const bool ar   = (g_not_arange == 0);
        long long total = nnz;
        long long stride = (long long)gridDim.x * blockDim.x;
        for (long long i = (long long)blockIdx.x * blockDim.x + tid;
             i < total; i += stride) {
            long long k = is64 ? ((const long long*)keysv)[i]
                               : (long long)((const int*)keysv)[i];
            unsigned okk; float ovv;
            if (ar) process_one<true >(k, valsv[i], F, okk, ovv);
            else    process_one<false>(k, valsv[i], F, okk, ovv);
            if (is64) {
                double* o = (double*)outv;
                o[i] = (double)okk; o[total + i] = (double)ovv;
            } else {
                float* o = (float*)outv;
                o[i] = (float)okk;  o[total + i] = ovv;
            }
        }
    }
}

extern "C" void kernel_launch(void* const* d_in, const int* in_sizes, int n_in,
                              void* d_out, int out_size) {
    // ---- classify inputs by element count (order-agnostic) ----
    long long s[16];
    int n = n_in < 16 ? n_in : 16;
    for (int i = 0; i < n; i++) s[i] = (long long)in_sizes[i];

    long long m1 = -1, m2 = -1;
    for (int i = 0; i < n; i++) {
        if (s[i] > m1) { m2 = m1; m1 = s[i]; }
        else if (s[i] > m2) { m2 = s[i]; }
    }

    int ik = -1, iv = -1;
    long long nnz_ll;
    int force64 = 0;
    if (m1 == m2) {
        for (int i = 0; i < n; i++)
            if (s[i] == m1) { if (ik < 0) ik = i; else if (iv < 0) iv = i; }
        nnz_ll = m1;
    } else {
        for (int i = 0; i < n; i++) {
            if (s[i] == m1 && ik < 0) ik = i;
            else if (s[i] == m1 / 2 && iv < 0) iv = i;
        }
        nnz_ll = m1 / 2;
        force64 = 1;
    }
    if (iv < 0) iv = ik;

    int ia = -1, ib = -1;
    for (int i = 0; i < n; i++) {
        if (i == ik || i == iv) continue;
        if (ia < 0) ia = i; else if (ib < 0) ib = i;
    }
    if (ib < 0) ib = ia;
    int iF = (s[ia] <= s[ib]) ? ia : ib;   // feature_ids (smaller)
    int iB = (iF == ia) ? ib : ia;         // bin_vals

    int nnz = (int)nnz_ll;
    int F = (int)(force64 ? s[iF] / 2 : s[iF]);
    if (F > MAX_F) F = MAX_F;
    if (F < 1) F = 1;

    const void*  keys = d_in[ik];
    const float* vals = (const float*)d_in[iv];
    const void*  fids = d_in[iF];
    const float* bins = (const float*)d_in[iB];

    int total_max = F * ROW;
    if (total_max < LUT_SIZE) total_max = LUT_SIZE;
    build_tables<<<(total_max + 255) / 256, 256>>>(fids, bins, F, total_max,
                                                   force64);

    // persistent launch: 1 CTA per SM, 1024 threads, F*16B dynamic smem
    int dev = 0;
    cudaGetDevice(&dev);
    int sms = 148;
    cudaDeviceGetAttribute(&sms, cudaDevAttrMultiProcessorCount, dev);
    if (sms < 1) sms = 148;
    size_t smem = (size_t)F * 16;
    cudaFuncSetAttribute(hashing_smem_kernel,
                         cudaFuncAttributeMaxDynamicSharedMemorySize,
                         (int)smem);
    hashing_smem_kernel<<<sms, 1024, smem>>>(keys, vals, nnz, d_out, F);
}

// round 11
// speedup vs baseline: 1.5352x; 1.5352x over previous
#include <cuda_runtime.h>
#include <cstdint>

// ----------------------------------------------------------------------------
// HashingDiscretizer — R11.
// Verified env: keys int32, output f32 concat [out_keys | out_vals] (2*nnz),
// feature_ids == arange(F) (runtime-verified; fallbacks kept).
// R11: independent per-lane gathers (no shuffles/smem), high occupancy.
//   level 1: 16B row of 8 bf16 splitters (rounded down) -> child c' >= c
//   level 2: 32B guarded leaf [bins[8c-1], bins[8c..8c+6]]; accept iff
//            guard < v (exact); rare decrement+reload otherwise.
// Gather: 48B / 2 wavefronts per calibrated element (was 64B / 4).
// ----------------------------------------------------------------------------

static constexpr int  LUT_SIZE = 65536;
static constexpr int  NBIN     = 63;
static constexpr int  ROW      = 72;        // legacy btree (fallback paths)
static constexpr int  MAX_F    = 8192;
static constexpr unsigned GOLDEN = 0x9E3779B9u;
static constexpr unsigned OUT_MASK_U = 0x3FFFFFu;        // (1<<22)-1

__device__ int g_is64 = 0;
__device__ int g_not_arange = 0;  // monotone 0->1 via atomicOr (deterministic)
__device__ unsigned short g_lut[LUT_SIZE];                  // fallback LUT
__device__ __align__(32) float g_btree[MAX_F * ROW];        // fallback btree
__device__ __align__(16) unsigned short g_spl16[MAX_F * 8]; // bf16 splitters
__device__ __align__(32) float g_leafg[MAX_F * 64];         // guarded leaves

// bf16 round toward -inf (stored splitter <= true splitter)
__device__ __forceinline__ unsigned short bf16_rd(float x) {
    unsigned b = __float_as_uint(x);
    unsigned hi = b >> 16;
    if ((b & 0x80000000u) && (b & 0xFFFFu)) hi++;   // negative: round away
    return (unsigned short)hi;
}

// ---- K1: fused probe + arange-check + LUT + legacy btree + spl16 + leaves --
__global__ void build_tables(const void* __restrict__ fids,
                             const float* __restrict__ bins,
                             int F, int force64) {
    int t = blockIdx.x * blockDim.x + threadIdx.x;

    const int* fw = (const int*)fids;
    const bool is64 = force64 || (fw[1] == 0 && fw[3] == 0);
    if (t == 0) g_is64 = is64 ? 1 : 0;

    const long long* f64p = (const long long*)fids;
    const int*       f32p = (const int*)fids;

    if (t < LUT_SIZE) {
        if (t < F) {
            long long fv = is64 ? f64p[t] : (long long)f32p[t];
            if (fv != (long long)t) atomicOr(&g_not_arange, 1);
        }
        long long key = (long long)t;
        int lo = 0, hi = F;
        while (lo < hi) {
            int mid = (lo + hi) >> 1;
            long long fv = is64 ? f64p[mid] : (long long)f32p[mid];
            if (fv < key) lo = mid + 1; else hi = mid;
        }
        int idx = lo < (F - 1) ? lo : (F - 1);
        long long fv = is64 ? f64p[idx] : (long long)f32p[idx];
        unsigned short v = (unsigned short)(idx & 0x7FFF);
        if (fv == key) v |= 0x8000u;
        g_lut[t] = v;
    }
    // legacy btree (fallback paths)
    if (t < F * ROW) {
        int f = t / ROW;
        int j = t - f * ROW;
        const float INF = __int_as_float(0x7f800000);
        float v;
        if (j < 8) {
            v = (j < 7) ? __ldg(&bins[f * NBIN + 8 * j + 7]) : INF;
        } else {
            int q = j - 8, l = q >> 3, p = q & 7;
            v = (p < 7) ? __ldg(&bins[f * NBIN + 8 * l + p]) : INF;
        }
        g_btree[t] = v;
    }
    // bf16 splitters: row r = [rd(s_0)..rd(s_6), +inf]
    if (t < F * 8) {
        int r = t >> 3, j = t & 7;
        unsigned short h = (j < 7) ? bf16_rd(__ldg(&bins[r * NBIN + 8 * j + 7]))
                                   : (unsigned short)0x7F80;   // +inf bf16
        g_spl16[t] = h;
    }
    // guarded leaves: row r = 8 leaves x [guard, b_{8m}..b_{8m+6}]
    if (t < F * 64) {
        int r = t >> 6, q = t & 63, m = q >> 3, p = q & 7;
        float v;
        if (p == 0) v = (m == 0) ? __int_as_float(0xFF800000)   // -inf
                                 : __ldg(&bins[r * NBIN + 8 * m - 1]);
        else        v = __ldg(&bins[r * NBIN + 8 * m + p - 1]);
        g_leafg[t] = v;
    }
}

// ---- generic per-element path (fallback configs + tails) -------------------
template <bool AR>
__device__ __forceinline__ void process_one(long long k, float v, int F,
                                            unsigned& okey, float& oval) {
    unsigned long long u = (unsigned long long)k;
    bool cal; int idx;
    if (AR) { cal = u < (unsigned long long)F; idx = (int)u; }
    else {
        if (u < (unsigned long long)LUT_SIZE) {
            unsigned short e = g_lut[u];
            cal = (e & 0x8000u) != 0; idx = (int)(e & 0x7FFFu);
        } else { cal = false; idx = 0; }
    }
    if (cal) {
        const float* nb = g_btree + idx * ROW;
        float4 s0 = *(const float4*)(nb);
        float4 s1 = *(const float4*)(nb + 4);
        int c = (s0.x < v) + (s0.y < v) + (s0.z < v) + (s0.w < v)
              + (s1.x < v) + (s1.y < v) + (s1.z < v) + (s1.w < v);
        const float* lf = nb + 8 + c * 8;
        float4 l0 = *(const float4*)(lf);
        float4 l1 = *(const float4*)(lf + 4);
        int bin = c * 8
              + (l0.x < v) + (l0.y < v) + (l0.z < v) + (l0.w < v)
              + (l1.x < v) + (l1.y < v) + (l1.z < v) + (l1.w < v);
        unsigned h = ((unsigned)u * GOLDEN + (unsigned)bin) * GOLDEN;
        okey = h & OUT_MASK_U; oval = 1.0f;
    } else {
        okey = (unsigned)(u & (unsigned long long)OUT_MASK_U);
        oval = v;
    }
}

// count of 8 bf16 (packed in uint4, low-half first) strictly < v
__device__ __forceinline__ int cnt8_bf16(uint4 w, float v) {
    float f0 = __uint_as_float(w.x << 16);
    float f1 = __uint_as_float(w.x & 0xFFFF0000u);
    float f2 = __uint_as_float(w.y << 16);
    float f3 = __uint_as_float(w.y & 0xFFFF0000u);
    float f4 = __uint_as_float(w.z << 16);
    float f5 = __uint_as_float(w.z & 0xFFFF0000u);
    float f6 = __uint_as_float(w.w << 16);
    float f7 = __uint_as_float(w.w & 0xFFFF0000u);
    return (f0 < v) + (f1 < v) + (f2 < v) + (f3 < v)
         + (f4 < v) + (f5 < v) + (f6 < v) + (f7 < v);
}

// exact guarded-leaf resolve: returns final bin
__device__ __forceinline__ int leaf_resolve(const float* __restrict__ base,
                                            int c, float v,
                                            float4 a, float4 b) {
    // a = [guard, b0, b1, b2], b = [b3, b4, b5, b6] of leaf c
    for (;;) {
        if (c > 0 && !(a.x < v)) {           // v <= guard -> true leaf < c
            c--;
            const float4* lp = (const float4*)(base + c * 8);
            a = lp[0]; b = lp[1];
            continue;
        }
        return c * 8 + (a.y < v) + (a.z < v) + (a.w < v)
                     + (b.x < v) + (b.y < v) + (b.z < v) + (b.w < v);
    }
}

// ---- hot path: int32 keys, f32 out, arange feature table, 2 elems/thread ---
__global__ void __launch_bounds__(256)
hashing_discretizer_kernel(const void* __restrict__ keysv,
                           const float* __restrict__ valsv,
                           int nnz, void* __restrict__ outv, int F) {
    const bool is64 = (g_is64 != 0);
    const bool ar   = (g_not_arange == 0);

    if (!is64 && ar) {
        const int*   keys = (const int*)keysv;
        const float* vals = valsv;
        float*       out  = (float*)outv;

        int t = blockIdx.x * blockDim.x + threadIdx.x;
        int i0 = t * 2;
        if (i0 >= nnz) return;

        if (i0 + 1 < nnz) {
            int2   kk = __ldcs((const int2*)(keys + i0));
            float2 vv = __ldcs((const float2*)(vals + i0));
            unsigned u0 = (unsigned)kk.x, u1 = (unsigned)kk.y;
            float v0 = vv.x, v1 = vv.y;
            bool cal0 = u0 < (unsigned)F, cal1 = u1 < (unsigned)F;

            // phase 1: bf16 splitter rows (16B each), batched @P loads
            uint4 sw0, sw1;
            if (cal0) sw0 = *(const uint4*)(g_spl16 + u0 * 8);
            if (cal1) sw1 = *(const uint4*)(g_spl16 + u1 * 8);
            int c0 = 0, c1 = 0;
            if (cal0) c0 = cnt8_bf16(sw0, v0);
            if (cal1) c1 = cnt8_bf16(sw1, v1);

            // phase 2: guarded leaves (32B each), batched @P loads
            float4 a0, b0, a1, b1;
            const float* base0 = g_leafg + u0 * 64;
            const float* base1 = g_leafg + u1 * 64;
            if (cal0) { const float4* lp = (const float4*)(base0 + c0 * 8);
                        a0 = lp[0]; b0 = lp[1]; }
            if (cal1) { const float4* lp = (const float4*)(base1 + c1 * 8);
                        a1 = lp[0]; b1 = lp[1]; }

            float ok0, ov0, ok1, ov1;
            if (cal0) {
                int bin = leaf_resolve(base0, c0, v0, a0, b0);
                unsigned h = (u0 * GOLDEN + (unsigned)bin) * GOLDEN;
                ok0 = (float)(h & OUT_MASK_U); ov0 = 1.0f;
            } else { ok0 = (float)(u0 & OUT_MASK_U); ov0 = v0; }
            if (cal1) {
                int bin = leaf_resolve(base1, c1, v1, a1, b1);
                unsigned h = (u1 * GOLDEN + (unsigned)bin) * GOLDEN;
                ok1 = (float)(h & OUT_MASK_U); ov1 = 1.0f;
            } else { ok1 = (float)(u1 & OUT_MASK_U); ov1 = v1; }

            __stcs((float2*)(out + i0),       make_float2(ok0, ok1));
            __stcs((float2*)(out + nnz + i0), make_float2(ov0, ov1));
        } else {
            unsigned ok; float ov;
            process_one<true>((long long)keys[i0], vals[i0], F, ok, ov);
            out[i0] = (float)ok;
            out[nnz + i0] = ov;
        }
    } else {
        // fallback configs: scalar, 2 elems/thread
        int t = blockIdx.x * blockDim.x + threadIdx.x;
        long long i0 = (long long)t * 2;
        long long total = nnz;
        if (i0 >= total) return;
        long long iend = (i0 + 2 < total) ? i0 + 2 : total;
        for (long long i = i0; i < iend; i++) {
            long long k = is64 ? ((const long long*)keysv)[i]
                               : (long long)((const int*)keysv)[i];
            unsigned okk; float ovv;
            if (ar) process_one<true >(k, valsv[i], F, okk, ovv);
            else    process_one<false>(k, valsv[i], F, okk, ovv);
            if (is64) {
                double* o = (double*)outv;
                o[i] = (double)okk; o[total + i] = (double)ovv;
            } else {
                float* o = (float*)outv;
                o[i] = (float)okk;  o[total + i] = ovv;
            }
        }
    }
}

extern "C" void kernel_launch(void* const* d_in, const int* in_sizes, int n_in,
                              void* d_out, int out_size) {
    // ---- classify inputs by element count (order-agnostic) ----
    long long s[16];
    int n = n_in < 16 ? n_in : 16;
    for (int i = 0; i < n; i++) s[i] = (long long)in_sizes[i];

    long long m1 = -1, m2 = -1;
    for (int i = 0; i < n; i++) {
        if (s[i] > m1) { m2 = m1; m1 = s[i]; }
        else if (s[i] > m2) { m2 = s[i]; }
    }

    int ik = -1, iv = -1;
    long long nnz_ll;
    int force64 = 0;
    if (m1 == m2) {
        for (int i = 0; i < n; i++)
            if (s[i] == m1) { if (ik < 0) ik = i; else if (iv < 0) iv = i; }
        nnz_ll = m1;
    } else {
        for (int i = 0; i < n; i++) {
            if (s[i] == m1 && ik < 0) ik = i;
            else if (s[i] == m1 / 2 && iv < 0) iv = i;
        }
        nnz_ll = m1 / 2;
        force64 = 1;
    }
    if (iv < 0) iv = ik;

    int ia = -1, ib = -1;
    for (int i = 0; i < n; i++) {
        if (i == ik || i == iv) continue;
        if (ia < 0) ia = i; else if (ib < 0) ib = i;
    }
    if (ib < 0) ib = ia;
    int iF = (s[ia] <= s[ib]) ? ia : ib;   // feature_ids (smaller)
    int iB = (iF == ia) ? ib : ia;         // bin_vals

    int nnz = (int)nnz_ll;
    int F = (int)(force64 ? s[iF] / 2 : s[iF]);
    if (F > MAX_F) F = MAX_F;
    if (F < 1) F = 1;

    const void*  keys = d_in[ik];
    const float* vals = (const float*)d_in[iv];
    const void*  fids = d_in[iF];
    const float* bins = (const float*)d_in[iB];

    int build_n = F * ROW;                 // largest table (F*72 > F*64)
    if (build_n < LUT_SIZE) build_n = LUT_SIZE;
    build_tables<<<(build_n + 255) / 256, 256>>>(fids, bins, F, force64);

    int nthreads = (nnz + 1) / 2;
    hashing_discretizer_kernel<<<(nthreads + 255) / 256, 256>>>(
        keys, vals, nnz, d_out, F);
}